// round 2
// baseline (speedup 1.0000x reference)
#include <cuda_runtime.h>
#include <cuda_bf16.h>

// ---------------------------------------------------------------------------
// RecurrentGCN (GConvGRU, single step, h0 = 0) on GB300.
//
// Simplifications (exact, from h0 == 0):
//   - all cheb_conv(h0, ...) terms == bias
//   - r gate is entirely unused (h0 * r == 0)
//   - h = (1 - z) * h_tilde
// Pipeline:
//   K1 init:   zero deg/cnt, pack Wbig[192][128] = [Wxz|Wxh] over K, bcomb[128]
//   K2 accum:  deg[row] += w (float atomics), cnt[col]++ (int atomics)
//   K3 scan:   dis = rsqrt(deg), exclusive scan cnt -> offs, wpos
//   K4 fill:   norm[e] = -dis[row]*w*dis[col]; CSR scatter by col
//   K5 prop1:  tx1 = prop(x)        (warp per node, CSR gather)
//   K6 prop2:  tx2 = 2*prop(tx1)-x  (warp per node, CSR gather)
//   K7 gemm:   y = [x|tx1|tx2] @ Wbig, gates, head -> out  (FFMA2 f32x2)
// ---------------------------------------------------------------------------

namespace {
constexpr int NN = 50000;
constexpr int EE = 800000;
}

__device__ float g_deg[NN];
__device__ float g_dis[NN];
__device__ int   g_cnt[NN];
__device__ int   g_offs[NN + 1];
__device__ int   g_wpos[NN];
__device__ int   g_src[EE];
__device__ float g_nrm[EE];
__device__ float g_tx1[NN * 64];
__device__ float g_tx2[NN * 64];
__device__ float g_Wbig[192 * 128];
__device__ float g_bcomb[128];

__device__ __forceinline__ unsigned long long pack2(float a, float b) {
  unsigned long long r;
  asm("mov.b64 %0, {%1,%2};" : "=l"(r) : "f"(a), "f"(b));
  return r;
}
__device__ __forceinline__ float2 unpack2(unsigned long long p) {
  float2 r;
  asm("mov.b64 {%0,%1}, %2;" : "=f"(r.x), "=f"(r.y) : "l"(p));
  return r;
}
__device__ __forceinline__ void fma2(unsigned long long& d, unsigned long long a,
                                     unsigned long long b, unsigned long long c) {
  asm("fma.rn.f32x2 %0, %1, %2, %3;" : "=l"(d) : "l"(a), "l"(b), "l"(c));
}
__device__ __forceinline__ float sigmoidf(float v) {
  return 1.0f / (1.0f + __expf(-v));
}

// ---------------------------------------------------------------------------
// K1: zero scratch + pack combined weight matrix / bias vector
// Wbig[c][n]: c = 64*k + ci (Chebyshev order k, input feat ci)
//             n < 64 -> z gate col n ; n >= 64 -> h-tilde gate col n-64
__global__ void k_init(const float* __restrict__ Wxz, const float* __restrict__ Wxh,
                       const float* __restrict__ bxz, const float* __restrict__ bhz,
                       const float* __restrict__ bxh, const float* __restrict__ bhh) {
  int idx = blockIdx.x * blockDim.x + threadIdx.x;
  if (idx < NN) { g_deg[idx] = 0.0f; g_cnt[idx] = 0; }
  if (idx < 192 * 128) {
    int c = idx >> 7, nn2 = idx & 127;
    int kblk = c >> 6, ci = c & 63;
    g_Wbig[idx] = (nn2 < 64) ? Wxz[kblk * 4096 + ci * 64 + nn2]
                             : Wxh[kblk * 4096 + ci * 64 + (nn2 - 64)];
  }
  if (idx < 128) {
    g_bcomb[idx] = (idx < 64) ? (bxz[idx] + bhz[idx])
                              : (bxh[idx - 64] + bhh[idx - 64]);
  }
}

// ---------------------------------------------------------------------------
// K2: weighted out-degree (by row) + in-degree counts (by col)
__global__ void k_edge_accum(const int* __restrict__ ei, const float* __restrict__ w) {
  int e = blockIdx.x * blockDim.x + threadIdx.x;
  if (e >= EE) return;
  atomicAdd(&g_deg[ei[e]], w[e]);
  atomicAdd(&g_cnt[ei[EE + e]], 1);
}

// ---------------------------------------------------------------------------
// K3: single-block scan (8 items/thread, 1024 threads) + dis = rsqrt(deg)
__device__ __forceinline__ int warp_incl_scan(int v, int lane) {
#pragma unroll
  for (int d = 1; d < 32; d <<= 1) {
    int t = __shfl_up_sync(0xFFFFFFFFu, v, d);
    if (lane >= d) v += t;
  }
  return v;
}

__global__ __launch_bounds__(1024) void k_scan() {
  constexpr int T = 1024, IPT = 8, CH = T * IPT;
  __shared__ int wsum[32];
  __shared__ int carry_s;
  int tid = threadIdx.x, lane = tid & 31, wid = tid >> 5;
  if (tid == 0) carry_s = 0;
  __syncthreads();
  int nCh = (NN + CH - 1) / CH;
  for (int ch = 0; ch < nCh; ch++) {
    int base = ch * CH + tid * IPT;
    int v[IPT];
#pragma unroll
    for (int j = 0; j < IPT; j++) {
      int i = base + j;
      if (i < NN) {
        v[j] = g_cnt[i];
        float dg = g_deg[i];
        g_dis[i] = (dg > 0.0f) ? rsqrtf(dg) : 0.0f;
      } else {
        v[j] = 0;
      }
    }
    int tsum = 0;
#pragma unroll
    for (int j = 0; j < IPT; j++) tsum += v[j];
    int incl = warp_incl_scan(tsum, lane);
    if (lane == 31) wsum[wid] = incl;
    __syncthreads();
    if (wid == 0) {
      int wv = wsum[lane];
      int wincl = warp_incl_scan(wv, lane);
      wsum[lane] = wincl - wv;  // exclusive warp offsets
    }
    __syncthreads();
    int run = carry_s + wsum[wid] + (incl - tsum);
#pragma unroll
    for (int j = 0; j < IPT; j++) {
      int i = base + j;
      if (i < NN) { g_offs[i] = run; g_wpos[i] = run; }
      run += v[j];
    }
    __syncthreads();
    if (tid == T - 1) carry_s = run;  // inclusive total so far
    __syncthreads();
  }
  if (tid == 0) g_offs[NN] = carry_s;
}

// ---------------------------------------------------------------------------
// K4: norm + CSR fill (scatter edges into per-col buckets)
__global__ void k_edge_fill(const int* __restrict__ ei, const float* __restrict__ w) {
  int e = blockIdx.x * blockDim.x + threadIdx.x;
  if (e >= EE) return;
  int r = ei[e], c = ei[EE + e];
  float nrm = -g_dis[r] * w[e] * g_dis[c];
  int p = atomicAdd(&g_wpos[c], 1);
  g_src[p] = r;
  g_nrm[p] = nrm;
}

// ---------------------------------------------------------------------------
// K5/K6: warp-per-node CSR gather. lane owns feature pair (2*lane, 2*lane+1).
__global__ __launch_bounds__(256) void k_prop1(const float* __restrict__ x) {
  int gw = (blockIdx.x * blockDim.x + threadIdx.x) >> 5;
  int lane = threadIdx.x & 31;
  if (gw >= NN) return;
  int s = g_offs[gw], e = g_offs[gw + 1];
  const float2* xf2 = reinterpret_cast<const float2*>(x);
  float ax = 0.f, ay = 0.f;
  int j = s;
  for (; j + 4 <= e; j += 4) {
    int s0 = g_src[j], s1 = g_src[j + 1], s2 = g_src[j + 2], s3 = g_src[j + 3];
    float n0 = g_nrm[j], n1 = g_nrm[j + 1], n2 = g_nrm[j + 2], n3 = g_nrm[j + 3];
    float2 v0 = xf2[s0 * 32 + lane];
    float2 v1 = xf2[s1 * 32 + lane];
    float2 v2 = xf2[s2 * 32 + lane];
    float2 v3 = xf2[s3 * 32 + lane];
    ax += n0 * v0.x; ay += n0 * v0.y;
    ax += n1 * v1.x; ay += n1 * v1.y;
    ax += n2 * v2.x; ay += n2 * v2.y;
    ax += n3 * v3.x; ay += n3 * v3.y;
  }
  for (; j < e; j++) {
    int s0 = g_src[j];
    float n0 = g_nrm[j];
    float2 v0 = xf2[s0 * 32 + lane];
    ax += n0 * v0.x; ay += n0 * v0.y;
  }
  reinterpret_cast<float2*>(g_tx1)[gw * 32 + lane] = make_float2(ax, ay);
}

__global__ __launch_bounds__(256) void k_prop2(const float* __restrict__ x) {
  int gw = (blockIdx.x * blockDim.x + threadIdx.x) >> 5;
  int lane = threadIdx.x & 31;
  if (gw >= NN) return;
  int s = g_offs[gw], e = g_offs[gw + 1];
  const float2* tf2 = reinterpret_cast<const float2*>(g_tx1);
  float ax = 0.f, ay = 0.f;
  int j = s;
  for (; j + 4 <= e; j += 4) {
    int s0 = g_src[j], s1 = g_src[j + 1], s2 = g_src[j + 2], s3 = g_src[j + 3];
    float n0 = g_nrm[j], n1 = g_nrm[j + 1], n2 = g_nrm[j + 2], n3 = g_nrm[j + 3];
    float2 v0 = tf2[s0 * 32 + lane];
    float2 v1 = tf2[s1 * 32 + lane];
    float2 v2 = tf2[s2 * 32 + lane];
    float2 v3 = tf2[s3 * 32 + lane];
    ax += n0 * v0.x; ay += n0 * v0.y;
    ax += n1 * v1.x; ay += n1 * v1.y;
    ax += n2 * v2.x; ay += n2 * v2.y;
    ax += n3 * v3.x; ay += n3 * v3.y;
  }
  for (; j < e; j++) {
    int s0 = g_src[j];
    float n0 = g_nrm[j];
    float2 v0 = tf2[s0 * 32 + lane];
    ax += n0 * v0.x; ay += n0 * v0.y;
  }
  float2 xv = reinterpret_cast<const float2*>(x)[gw * 32 + lane];
  // tx2 = 2 * prop(tx1) - x
  reinterpret_cast<float2*>(g_tx2)[gw * 32 + lane] =
      make_float2(2.0f * ax - xv.x, 2.0f * ay - xv.y);
}

// ---------------------------------------------------------------------------
// K7: fused GEMM (64 nodes x 128 outs x 192 K) + gates + linear head
// Thread layout: nIdx = tid&15 owns n = 2*nIdx + 32*j + {0,1}, j in 0..3
//                mIdx = tid>>4 owns nodes mIdx*4 + i, i in 0..3
// n in [0,64) -> z gate (j=0,1), n in [64,128) -> h-tilde gate (j=2,3)
__global__ __launch_bounds__(256) void k_gemm(const float* __restrict__ x,
                                              const float* __restrict__ Wlin,
                                              const float* __restrict__ blin,
                                              float* __restrict__ out) {
  __shared__ float Ws[32 * 128];      // 16 KB: W chunk, rows=k, cols=n
  __shared__ float Ts[64 * 33];       // 8.25 KB: T chunk, padded stride 33
  __shared__ float Hs[64 * 65];       // 16.6 KB: tanh(h) for head
  int tid = threadIdx.x;
  int nIdx = tid & 15;
  int mIdx = tid >> 4;
  int blockBase = blockIdx.x * 64;

  unsigned long long acc[4][4];
#pragma unroll
  for (int i = 0; i < 4; i++)
#pragma unroll
    for (int j = 0; j < 4; j++) acc[i][j] = 0ull;

#pragma unroll 1
  for (int ch = 0; ch < 6; ch++) {
    // stage W chunk (rows ch*32 .. ch*32+31 of Wbig), contiguous
    const float4* wsrc = reinterpret_cast<const float4*>(g_Wbig + ch * 32 * 128);
    float4* wdst = reinterpret_cast<float4*>(Ws);
#pragma unroll
    for (int j = 0; j < 4; j++) wdst[tid + j * 256] = wsrc[tid + j * 256];
    // stage T chunk: features [ch*32 global k) of [x|tx1|tx2]
    const float* src = (ch < 2) ? x : (ch < 4) ? g_tx1 : g_tx2;
    int koff = (ch & 1) * 32;
    int row = tid >> 2, seg = tid & 3;
    int node = blockBase + row;
    if (node >= NN) node = NN - 1;
    const float4* trow = reinterpret_cast<const float4*>(src + node * 64 + koff);
    float4 a = trow[seg * 2], b = trow[seg * 2 + 1];
    float* tdst = Ts + row * 33 + seg * 8;
    tdst[0] = a.x; tdst[1] = a.y; tdst[2] = a.z; tdst[3] = a.w;
    tdst[4] = b.x; tdst[5] = b.y; tdst[6] = b.z; tdst[7] = b.w;
    __syncthreads();

#pragma unroll
    for (int k = 0; k < 32; k++) {
      unsigned long long w2[4];
#pragma unroll
      for (int j = 0; j < 4; j++)
        w2[j] = *reinterpret_cast<const unsigned long long*>(
            &Ws[k * 128 + nIdx * 2 + j * 32]);
#pragma unroll
      for (int i = 0; i < 4; i++) {
        float tv = Ts[(mIdx * 4 + i) * 33 + k];
        unsigned long long t2 = pack2(tv, tv);
#pragma unroll
        for (int j = 0; j < 4; j++) fma2(acc[i][j], t2, w2[j], acc[i][j]);
      }
    }
    __syncthreads();
  }

  // ---- gate epilogue: z = sigmoid(yz+b), ht = tanh(yh+b), store tanh((1-z)*ht)
  float2 bz[2], bh[2];
#pragma unroll
  for (int jj = 0; jj < 2; jj++) {
    bz[jj] = *reinterpret_cast<const float2*>(&g_bcomb[nIdx * 2 + jj * 32]);
    bh[jj] = *reinterpret_cast<const float2*>(&g_bcomb[64 + nIdx * 2 + jj * 32]);
  }
#pragma unroll
  for (int i = 0; i < 4; i++) {
    int m = mIdx * 4 + i;
#pragma unroll
    for (int jj = 0; jj < 2; jj++) {
      float2 az = unpack2(acc[i][jj]);       // z-gate pre-activation pair
      float2 ah = unpack2(acc[i][jj + 2]);   // h-gate pre-activation pair
      float z0 = sigmoidf(az.x + bz[jj].x);
      float z1 = sigmoidf(az.y + bz[jj].y);
      float h0 = tanhf(ah.x + bh[jj].x);
      float h1 = tanhf(ah.y + bh[jj].y);
      float t0 = tanhf((1.0f - z0) * h0);
      float t1 = tanhf((1.0f - z1) * h1);
      int d = nIdx * 2 + jj * 32;
      Hs[m * 65 + d] = t0;
      Hs[m * 65 + d + 1] = t1;
    }
  }
  __syncthreads();

  // ---- head: out = sigmoid(tanh(h) @ Wlin + blin); warp reduces 64-dot
  int lane = tid & 31, wq = tid >> 5;
  float w00 = Wlin[lane * 2 + 0], w01 = Wlin[lane * 2 + 1];
  float w10 = Wlin[(lane + 32) * 2 + 0], w11 = Wlin[(lane + 32) * 2 + 1];
  float bl0 = blin[0], bl1 = blin[1];
#pragma unroll
  for (int q = 0; q < 8; q++) {
    int m = wq * 8 + q;
    int node = blockBase + m;
    float a0 = Hs[m * 65 + lane], a1 = Hs[m * 65 + lane + 32];
    float v0 = a0 * w00 + a1 * w10;
    float v1 = a0 * w01 + a1 * w11;
#pragma unroll
    for (int d = 16; d; d >>= 1) {
      v0 += __shfl_xor_sync(0xFFFFFFFFu, v0, d);
      v1 += __shfl_xor_sync(0xFFFFFFFFu, v1, d);
    }
    if (lane == 0 && node < NN) {
      out[node * 2 + 0] = sigmoidf(v0 + bl0);
      out[node * 2 + 1] = sigmoidf(v1 + bl1);
    }
  }
}

// ---------------------------------------------------------------------------
extern "C" void kernel_launch(void* const* d_in, const int* in_sizes, int n_in,
                              void* d_out, int out_size) {
  const float* x    = (const float*)d_in[0];
  const int*   ei   = (const int*)d_in[1];
  const float* w    = (const float*)d_in[2];
  const float* Wxz  = (const float*)d_in[3];
  const float* bxz  = (const float*)d_in[4];
  const float* bhz  = (const float*)d_in[6];
  const float* Wxh  = (const float*)d_in[11];
  const float* bxh  = (const float*)d_in[12];
  const float* bhh  = (const float*)d_in[14];
  const float* Wlin = (const float*)d_in[15];
  const float* blin = (const float*)d_in[16];
  float* out = (float*)d_out;

  k_init<<<(NN + 255) / 256, 256>>>(Wxz, Wxh, bxz, bhz, bxh, bhh);
  k_edge_accum<<<(EE + 255) / 256, 256>>>(ei, w);
  k_scan<<<1, 1024>>>();
  k_edge_fill<<<(EE + 255) / 256, 256>>>(ei, w);
  k_prop1<<<(NN * 32 + 255) / 256, 256>>>(x);
  k_prop2<<<(NN * 32 + 255) / 256, 256>>>(x);
  k_gemm<<<(NN + 63) / 64, 256>>>(x, Wlin, blin, out);
}